// round 11
// baseline (speedup 1.0000x reference)
#include <cuda_runtime.h>
#include <cuda_fp16.h>
#include <cstdint>
#include <math.h>

#define BSZ     256
#define GRID_G  49
#define LSTMH   512
#define CNNC    2048
#define PROJ    512
#define M_TOTAL (BSZ * GRID_G)   /* 12544 */

#define A_ELEMS (M_TOTAL * CNNC)  /* 25,690,112 */
#define B_ELEMS (PROJ * CNNC)     /* 1,048,576  */

// Scratch (no allocation allowed -> __device__ globals)
__device__ float g_H[BSZ * PROJ];                 // H' = lstm@Wl^T + bl + bc
__device__ float g_z[M_TOTAL];                    // logits
__device__ __align__(16) __half g_Af16[A_ELEMS];  // cnn_feat fp16 (51MB, L2-resident)
__device__ __align__(16) __half g_Bf16[B_ELEMS];  // W_cnn fp16 (2MB)

__device__ __forceinline__ uint32_t pack_h2(float lo, float hi) {
    __half2 h = __floats2half2_rn(lo, hi);
    return *reinterpret_cast<uint32_t*>(&h);
}
__device__ __forceinline__ float tanh_ap(float x) {
    float y;
    asm("tanh.approx.f32 %0, %1;" : "=f"(y) : "f"(x));
    return y;
}

// ===========================================================================
// Kernel 1 (prep): blocks 0..127 H' GEMM + zero g_z; rest convert to fp16.
// Conversion: 4 independent 8-float chunks per thread (8 float4 loads in
// flight), __ldcs evict-first reads (A-f32 is read-once; keep L2 for f16).
// ===========================================================================
#define H_BLOCKS 128
#define TCH (A_ELEMS / 8 + B_ELEMS / 8)          /* 3,342,336 chunks */
#define ACH (A_ELEMS / 8)
#define CONV_BLOCKS ((TCH + 1023) / 1024)        /* 3264 */

__device__ __forceinline__ void conv_load(long idx8,
                                          const float* __restrict__ A,
                                          const float* __restrict__ Bw,
                                          float4& v0, float4& v1)
{
    const float* src = (idx8 < ACH) ? (A + idx8 * 8) : (Bw + (idx8 - ACH) * 8);
    v0 = __ldcs(reinterpret_cast<const float4*>(src));
    v1 = __ldcs(reinterpret_cast<const float4*>(src) + 1);
}
__device__ __forceinline__ void conv_store(long idx8, float4 v0, float4 v1)
{
    __half* dst = (idx8 < ACH) ? (g_Af16 + idx8 * 8) : (g_Bf16 + (idx8 - ACH) * 8);
    *reinterpret_cast<uint4*>(dst) =
        make_uint4(pack_h2(v0.x, v0.y), pack_h2(v0.z, v0.w),
                   pack_h2(v1.x, v1.y), pack_h2(v1.z, v1.w));
}

__global__ __launch_bounds__(256) void prep_kernel(
    const float* __restrict__ X,
    const float* __restrict__ W,
    const float* __restrict__ bl,
    const float* __restrict__ bc,
    const float* __restrict__ A,
    const float* __restrict__ Bw)
{
    __shared__ float As[32 * 129];
    __shared__ float Bs[32 * 129];
    const int t = threadIdx.x;

    if (blockIdx.x >= H_BLOCKS) {
        long base = (long)(blockIdx.x - H_BLOCKS) * 1024 + t;
        float4 v0[4], v1[4];
        bool ok[4];
        #pragma unroll
        for (int j = 0; j < 4; j++) {
            long idx = base + 256 * j;
            ok[j] = idx < TCH;
            if (ok[j]) conv_load(idx, A, Bw, v0[j], v1[j]);
        }
        #pragma unroll
        for (int j = 0; j < 4; j++)
            if (ok[j]) conv_store(base + 256 * j, v0[j], v1[j]);
        return;
    }

    // ---- H' GEMM (blocks 0..127) ----
    const int hb = blockIdx.x;
    const int mBase = (hb & 7) * 32;
    const int nBase = (hb >> 3) * 32;

    int flat = hb * 256 + t;
    if (flat < M_TOTAL) g_z[flat] = 0.0f;

    const int row = t >> 3;
    const int fc  = t & 7;
    const int ty  = t >> 4;
    const int tx  = t & 15;

    const float* xp = X + (size_t)(mBase + row) * LSTMH;
    const float* wp = W + (size_t)(nBase + row) * LSTMH;

    float acc[2][2] = {{0.f, 0.f}, {0.f, 0.f}};
    float4 pa[4], pb[4];

    #pragma unroll
    for (int i = 0; i < 4; i++) {
        pa[i] = *reinterpret_cast<const float4*>(xp + (fc + 8 * i) * 4);
        pb[i] = *reinterpret_cast<const float4*>(wp + (fc + 8 * i) * 4);
    }

    for (int c = 0; c < 4; c++) {
        if (c) __syncthreads();
        #pragma unroll
        for (int i = 0; i < 4; i++) {
            int base = row * 129 + (fc + 8 * i) * 4;
            As[base + 0] = pa[i].x; As[base + 1] = pa[i].y;
            As[base + 2] = pa[i].z; As[base + 3] = pa[i].w;
            Bs[base + 0] = pb[i].x; Bs[base + 1] = pb[i].y;
            Bs[base + 2] = pb[i].z; Bs[base + 3] = pb[i].w;
        }
        __syncthreads();
        if (c < 3) {
            int k0 = (c + 1) * 128;
            #pragma unroll
            for (int i = 0; i < 4; i++) {
                pa[i] = *reinterpret_cast<const float4*>(xp + k0 + (fc + 8 * i) * 4);
                pb[i] = *reinterpret_cast<const float4*>(wp + k0 + (fc + 8 * i) * 4);
            }
        }
        #pragma unroll 8
        for (int k = 0; k < 128; k++) {
            float a0 = As[(ty * 2 + 0) * 129 + k];
            float a1 = As[(ty * 2 + 1) * 129 + k];
            float b0 = Bs[(tx * 2 + 0) * 129 + k];
            float b1 = Bs[(tx * 2 + 1) * 129 + k];
            acc[0][0] += a0 * b0; acc[0][1] += a0 * b1;
            acc[1][0] += a1 * b0; acc[1][1] += a1 * b1;
        }
    }

    #pragma unroll
    for (int i = 0; i < 2; i++)
        #pragma unroll
        for (int j = 0; j < 2; j++) {
            int col = nBase + tx * 2 + j;
            g_H[(size_t)(mBase + ty * 2 + i) * PROJ + col] = acc[i][j] + bl[col] + bc[col];
        }
}

// ===========================================================================
// Kernel 2: fp16 mma m16n8k16, cp.async 3-slot ring, K-chunk 64 halves
// (128B rows, XOR SW128 swizzle). 32 stages, 1 barrier/stage.
// BM=BN=128, 8 warps (2M x 4N), warp tile 64x32, ldmatrix.x4.
// grid (4, 98): col tile fastest; A fp16 (51MB) is L2-resident.
// ===========================================================================
#define KCH    64
#define NSTG   (CNNC / KCH)               /* 32 */
#define STG_B  (2 * 128 * 128)            /* 32768 */
#define NRING  3
#define ATT_SMEM (NRING * STG_B + 128)

__device__ __forceinline__ void ldsm_x4(uint32_t& r0, uint32_t& r1,
                                        uint32_t& r2, uint32_t& r3, uint32_t addr)
{
    asm volatile("ldmatrix.sync.aligned.m8n8.x4.shared.b16 {%0,%1,%2,%3}, [%4];"
                 : "=r"(r0), "=r"(r1), "=r"(r2), "=r"(r3) : "r"(addr));
}
__device__ __forceinline__ void mma_f16(float c[4], const uint32_t a[4], const uint32_t b[2])
{
    asm volatile(
        "mma.sync.aligned.m16n8k16.row.col.f32.f16.f16.f32 "
        "{%0,%1,%2,%3}, {%4,%5,%6,%7}, {%8,%9}, {%0,%1,%2,%3};"
        : "+f"(c[0]), "+f"(c[1]), "+f"(c[2]), "+f"(c[3])
        : "r"(a[0]), "r"(a[1]), "r"(a[2]), "r"(a[3]), "r"(b[0]), "r"(b[1]));
}
__device__ __forceinline__ void cp_async16(uint32_t sdst, const void* gsrc) {
    asm volatile("cp.async.cg.shared.global [%0], [%1], 16;" :: "r"(sdst), "l"(gsrc) : "memory");
}
__device__ __forceinline__ void cp_commit() { asm volatile("cp.async.commit_group;" ::: "memory"); }
__device__ __forceinline__ void cp_wait1()  { asm volatile("cp.async.wait_group 1;"  ::: "memory"); }

__global__ __launch_bounds__(256, 2) void attn_gemm_kernel(
    const float* __restrict__ w_attn)
{
    extern __shared__ __align__(128) char smem[];
    const uint32_t sb = ((uint32_t)__cvta_generic_to_shared(smem) + 127u) & ~127u;

    const int t       = threadIdx.x;
    const int lane    = t & 31;
    const int wid     = t >> 5;
    const int warpM   = wid >> 2;
    const int warpN   = wid & 3;
    const int colBase = blockIdx.x * 128;
    const int rowBase = blockIdx.y * 128;

    uint32_t baseA[4], rxA[4];
    const uint32_t kqA = (uint32_t)(((lane >> 4) & 1) * 16);
    #pragma unroll
    for (int mi = 0; mi < 4; mi++) {
        int r = warpM * 64 + mi * 16 + (lane & 15);
        baseA[mi] = (uint32_t)(r * 128);
        rxA[mi]   = (uint32_t)((r & 7) * 16);
    }
    uint32_t baseB[2], rxB[2];
    const uint32_t kqB = (uint32_t)(((lane >> 3) & 1) * 16);
    #pragma unroll
    for (int np = 0; np < 2; np++) {
        int r = warpN * 32 + np * 16 + ((lane >> 4) & 1) * 8 + (lane & 7);
        baseB[np] = (uint32_t)(r * 128);
        rxB[np]   = (uint32_t)((r & 7) * 16);
    }

    float acc[4][4][4];
    #pragma unroll
    for (int mi = 0; mi < 4; mi++)
        #pragma unroll
        for (int ni = 0; ni < 4; ni++)
            #pragma unroll
            for (int c = 0; c < 4; c++) acc[mi][ni][c] = 0.0f;

    const __half* gA = g_Af16 + (size_t)rowBase * CNNC;
    const __half* gB = g_Bf16 + (size_t)colBase * CNNC;

    auto load_stage = [&](int slot, int kt) {
        const uint32_t aDst = sb + slot * STG_B;
        const uint32_t bDst = aDst + 128 * 128;
        const int kOff = kt * KCH;
        #pragma unroll
        for (int j = 0; j < 4; j++) {
            int c   = t + 256 * j;
            int row = c >> 3;
            int ch  = c & 7;
            uint32_t x = (uint32_t)(ch * 16) ^ (uint32_t)((row & 7) * 16);
            uint32_t d = (uint32_t)(row * 128) + x;
            cp_async16(aDst + d, gA + (size_t)row * CNNC + kOff + ch * 8);
            cp_async16(bDst + d, gB + (size_t)row * CNNC + kOff + ch * 8);
        }
    };

    load_stage(0, 0); cp_commit();
    load_stage(1, 1); cp_commit();

    for (int kt = 0; kt < NSTG; kt++) {
        cp_wait1();
        __syncthreads();

        if (kt + 2 < NSTG) load_stage((kt + 2) % NRING, kt + 2);
        cp_commit();

        const uint32_t aBase = sb + (kt % NRING) * STG_B;
        const uint32_t bBase = aBase + 128 * 128;
        #pragma unroll
        for (int ks = 0; ks < 4; ks++) {
            const uint32_t kxA = (uint32_t)(ks * 32) + kqA;
            const uint32_t kxB = (uint32_t)(ks * 32) + kqB;
            uint32_t af[4][4];
            uint32_t bf[4][2];
            #pragma unroll
            for (int mi = 0; mi < 4; mi++)
                ldsm_x4(af[mi][0], af[mi][1], af[mi][2], af[mi][3],
                        aBase + baseA[mi] + (kxA ^ rxA[mi]));
            #pragma unroll
            for (int np = 0; np < 2; np++) {
                uint32_t r0, r1, r2, r3;
                ldsm_x4(r0, r1, r2, r3, bBase + baseB[np] + (kxB ^ rxB[np]));
                bf[np * 2 + 0][0] = r0; bf[np * 2 + 0][1] = r1;
                bf[np * 2 + 1][0] = r2; bf[np * 2 + 1][1] = r3;
            }
            #pragma unroll
            for (int mi = 0; mi < 4; mi++)
                #pragma unroll
                for (int ni = 0; ni < 4; ni++)
                    mma_f16(acc[mi][ni], af[mi], bf[ni]);
        }
    }

    // Epilogue: z[r] += sum_p tanh(V[r,p] + H'[b,p]) * w_attn[p]
    const int tig = lane & 3;
    const float* wcol = w_attn + colBase + warpN * 32;
    #pragma unroll
    for (int mi = 0; mi < 4; mi++) {
        #pragma unroll
        for (int h = 0; h < 2; h++) {
            int r = rowBase + warpM * 64 + mi * 16 + h * 8 + (lane >> 2);
            int bidx = r / GRID_G;
            const float* Hrow = g_H + (size_t)bidx * PROJ + colBase + warpN * 32;
            float s = 0.0f;
            #pragma unroll
            for (int ni = 0; ni < 4; ni++) {
                int p = ni * 8 + tig * 2;
                float v0 = acc[mi][ni][h * 2 + 0] + __ldg(Hrow + p);
                float v1 = acc[mi][ni][h * 2 + 1] + __ldg(Hrow + p + 1);
                s += tanh_ap(v0) * __ldg(wcol + p) + tanh_ap(v1) * __ldg(wcol + p + 1);
            }
            s += __shfl_xor_sync(0xffffffffu, s, 1);
            s += __shfl_xor_sync(0xffffffffu, s, 2);
            if (tig == 0) atomicAdd(&g_z[r], s);
        }
    }
}

// ===========================================================================
// Kernel 3: scramble + row softmax
// ===========================================================================
__global__ __launch_bounds__(64) void softmax_kernel(float* __restrict__ out)
{
    __shared__ float red[64];
    const int i = blockIdx.x;
    const int t = threadIdx.x;

    float v = -INFINITY;
    if (t < GRID_G) {
        int k = i * GRID_G + t;
        v = g_z[(k % BSZ) * GRID_G + (k / BSZ)];
    }
    red[t] = v;
    __syncthreads();
    #pragma unroll
    for (int s = 32; s > 0; s >>= 1) {
        if (t < s) red[t] = fmaxf(red[t], red[t + s]);
        __syncthreads();
    }
    float mx = red[0];
    __syncthreads();

    float e = (t < GRID_G) ? expf(v - mx) : 0.0f;
    red[t] = e;
    __syncthreads();
    #pragma unroll
    for (int s = 32; s > 0; s >>= 1) {
        if (t < s) red[t] += red[t + s];
        __syncthreads();
    }
    float sum = red[0];
    if (t < GRID_G) out[i * GRID_G + t] = e / sum;
}

// ===========================================================================
extern "C" void kernel_launch(void* const* d_in, const int* in_sizes, int n_in,
                              void* d_out, int out_size)
{
    const float* lstm = (const float*)d_in[0];
    const float* cnn  = (const float*)d_in[1];
    const float* Wl   = (const float*)d_in[2];
    const float* bl   = (const float*)d_in[3];
    const float* Wc   = (const float*)d_in[4];
    const float* bc   = (const float*)d_in[5];
    const float* wa   = (const float*)d_in[6];
    float* out = (float*)d_out;

    cudaFuncSetAttribute(attn_gemm_kernel,
                         cudaFuncAttributeMaxDynamicSharedMemorySize, ATT_SMEM);

    prep_kernel<<<H_BLOCKS + CONV_BLOCKS, 256>>>(lstm, Wl, bl, bc, cnn, Wc);
    attn_gemm_kernel<<<dim3(4, 98), 256, ATT_SMEM>>>(wa);
    softmax_kernel<<<256, 64>>>(out);
}

// round 13
// speedup vs baseline: 1.0046x; 1.0046x over previous
#include <cuda_runtime.h>
#include <cuda_fp16.h>
#include <cstdint>
#include <math.h>

#define BSZ     256
#define GRID_G  49
#define LSTMH   512
#define CNNC    2048
#define PROJ    512
#define M_TOTAL (BSZ * GRID_G)   /* 12544 */

#define A_ELEMS (M_TOTAL * CNNC)  /* 25,690,112 */
#define B_ELEMS (PROJ * CNNC)     /* 1,048,576  */

// Scratch (no allocation allowed -> __device__ globals)
__device__ float g_H[BSZ * PROJ];                 // H' = lstm@Wl^T + bl + bc
__device__ float g_z[M_TOTAL];                    // logits
__device__ __align__(16) __half g_Af16[A_ELEMS];  // cnn_feat fp16 (51MB, L2-resident)
__device__ __align__(16) __half g_Bf16[B_ELEMS];  // W_cnn fp16 (2MB)

__device__ __forceinline__ uint32_t pack_h2(float lo, float hi) {
    __half2 h = __floats2half2_rn(lo, hi);
    return *reinterpret_cast<uint32_t*>(&h);
}
__device__ __forceinline__ float tanh_ap(float x) {
    float y;
    asm("tanh.approx.f32 %0, %1;" : "=f"(y) : "f"(x));
    return y;
}

// ===========================================================================
// Kernel 1 (prep): blocks 0..127 H' GEMM + zero g_z; then branch-free
// fp16 conversion: A-blocks and B-blocks in disjoint ranges, 2 chunks/thread
// (R9 sweet spot: plain loads, no predication).
// ===========================================================================
#define H_BLOCKS 128
#define ACH (A_ELEMS / 8)                 /* 3,211,264  (= 6272 * 512) */
#define BCH (B_ELEMS / 8)                 /* 131,072    (= 256  * 512) */
#define A_CONV_BLOCKS (ACH / 512)         /* 6272 exact */
#define B_CONV_BLOCKS (BCH / 512)         /* 256 exact  */
#define CONV_BLOCKS (A_CONV_BLOCKS + B_CONV_BLOCKS)

__device__ __forceinline__ void conv2(const float* __restrict__ src,
                                      __half* __restrict__ dst, long base)
{
    // two independent 8-float chunks: base and base+256 (4 float4 loads in flight)
    const float4* s0 = reinterpret_cast<const float4*>(src + base * 8);
    const float4* s1 = reinterpret_cast<const float4*>(src + (base + 256) * 8);
    float4 a0 = s0[0], a1 = s0[1];
    float4 b0 = s1[0], b1 = s1[1];
    *reinterpret_cast<uint4*>(dst + base * 8) =
        make_uint4(pack_h2(a0.x, a0.y), pack_h2(a0.z, a0.w),
                   pack_h2(a1.x, a1.y), pack_h2(a1.z, a1.w));
    *reinterpret_cast<uint4*>(dst + (base + 256) * 8) =
        make_uint4(pack_h2(b0.x, b0.y), pack_h2(b0.z, b0.w),
                   pack_h2(b1.x, b1.y), pack_h2(b1.z, b1.w));
}

__global__ __launch_bounds__(256) void prep_kernel(
    const float* __restrict__ X,
    const float* __restrict__ W,
    const float* __restrict__ bl,
    const float* __restrict__ bc,
    const float* __restrict__ A,
    const float* __restrict__ Bw)
{
    __shared__ float As[32 * 129];
    __shared__ float Bs[32 * 129];
    const int t = threadIdx.x;

    if (blockIdx.x >= H_BLOCKS) {
        int cb = blockIdx.x - H_BLOCKS;
        if (cb < A_CONV_BLOCKS) {
            conv2(A, g_Af16, (long)cb * 512 + t);
        } else {
            conv2(Bw, g_Bf16, (long)(cb - A_CONV_BLOCKS) * 512 + t);
        }
        return;
    }

    // ---- H' GEMM (blocks 0..127) ----
    const int hb = blockIdx.x;
    const int mBase = (hb & 7) * 32;
    const int nBase = (hb >> 3) * 32;

    int flat = hb * 256 + t;
    if (flat < M_TOTAL) g_z[flat] = 0.0f;

    const int row = t >> 3;
    const int fc  = t & 7;
    const int ty  = t >> 4;
    const int tx  = t & 15;

    const float* xp = X + (size_t)(mBase + row) * LSTMH;
    const float* wp = W + (size_t)(nBase + row) * LSTMH;

    float acc[2][2] = {{0.f, 0.f}, {0.f, 0.f}};
    float4 pa[4], pb[4];

    #pragma unroll
    for (int i = 0; i < 4; i++) {
        pa[i] = *reinterpret_cast<const float4*>(xp + (fc + 8 * i) * 4);
        pb[i] = *reinterpret_cast<const float4*>(wp + (fc + 8 * i) * 4);
    }

    for (int c = 0; c < 4; c++) {
        if (c) __syncthreads();
        #pragma unroll
        for (int i = 0; i < 4; i++) {
            int base = row * 129 + (fc + 8 * i) * 4;
            As[base + 0] = pa[i].x; As[base + 1] = pa[i].y;
            As[base + 2] = pa[i].z; As[base + 3] = pa[i].w;
            Bs[base + 0] = pb[i].x; Bs[base + 1] = pb[i].y;
            Bs[base + 2] = pb[i].z; Bs[base + 3] = pb[i].w;
        }
        __syncthreads();
        if (c < 3) {
            int k0 = (c + 1) * 128;
            #pragma unroll
            for (int i = 0; i < 4; i++) {
                pa[i] = *reinterpret_cast<const float4*>(xp + k0 + (fc + 8 * i) * 4);
                pb[i] = *reinterpret_cast<const float4*>(wp + k0 + (fc + 8 * i) * 4);
            }
        }
        #pragma unroll 8
        for (int k = 0; k < 128; k++) {
            float a0 = As[(ty * 2 + 0) * 129 + k];
            float a1 = As[(ty * 2 + 1) * 129 + k];
            float b0 = Bs[(tx * 2 + 0) * 129 + k];
            float b1 = Bs[(tx * 2 + 1) * 129 + k];
            acc[0][0] += a0 * b0; acc[0][1] += a0 * b1;
            acc[1][0] += a1 * b0; acc[1][1] += a1 * b1;
        }
    }

    #pragma unroll
    for (int i = 0; i < 2; i++)
        #pragma unroll
        for (int j = 0; j < 2; j++) {
            int col = nBase + tx * 2 + j;
            g_H[(size_t)(mBase + ty * 2 + i) * PROJ + col] = acc[i][j] + bl[col] + bc[col];
        }
}

// ===========================================================================
// Kernel 2: fp16 mma m16n8k16, cp.async 3-slot ring, K-chunk 64 halves
// (128B rows, XOR SW128 swizzle). 32 stages, 1 barrier/stage.
// BM=BN=128, 8 warps (2M x 4N), warp tile 64x32, ldmatrix.x4.
// B fragments double-buffered across ks to hide LDSM latency in-warp.
// grid (4, 98): col tile fastest; A fp16 (51MB) is L2-resident.
// ===========================================================================
#define KCH    64
#define NSTG   (CNNC / KCH)               /* 32 */
#define STG_B  (2 * 128 * 128)            /* 32768 */
#define NRING  3
#define ATT_SMEM (NRING * STG_B + 128)

__device__ __forceinline__ void ldsm_x4(uint32_t& r0, uint32_t& r1,
                                        uint32_t& r2, uint32_t& r3, uint32_t addr)
{
    asm volatile("ldmatrix.sync.aligned.m8n8.x4.shared.b16 {%0,%1,%2,%3}, [%4];"
                 : "=r"(r0), "=r"(r1), "=r"(r2), "=r"(r3) : "r"(addr));
}
__device__ __forceinline__ void mma_f16(float c[4], const uint32_t a[4], const uint32_t b[2])
{
    asm volatile(
        "mma.sync.aligned.m16n8k16.row.col.f32.f16.f16.f32 "
        "{%0,%1,%2,%3}, {%4,%5,%6,%7}, {%8,%9}, {%0,%1,%2,%3};"
        : "+f"(c[0]), "+f"(c[1]), "+f"(c[2]), "+f"(c[3])
        : "r"(a[0]), "r"(a[1]), "r"(a[2]), "r"(a[3]), "r"(b[0]), "r"(b[1]));
}
__device__ __forceinline__ void cp_async16(uint32_t sdst, const void* gsrc) {
    asm volatile("cp.async.cg.shared.global [%0], [%1], 16;" :: "r"(sdst), "l"(gsrc) : "memory");
}
__device__ __forceinline__ void cp_commit() { asm volatile("cp.async.commit_group;" ::: "memory"); }
__device__ __forceinline__ void cp_wait1()  { asm volatile("cp.async.wait_group 1;"  ::: "memory"); }

__global__ __launch_bounds__(256, 2) void attn_gemm_kernel(
    const float* __restrict__ w_attn)
{
    extern __shared__ __align__(128) char smem[];
    const uint32_t sb = ((uint32_t)__cvta_generic_to_shared(smem) + 127u) & ~127u;

    const int t       = threadIdx.x;
    const int lane    = t & 31;
    const int wid     = t >> 5;
    const int warpM   = wid >> 2;
    const int warpN   = wid & 3;
    const int colBase = blockIdx.x * 128;
    const int rowBase = blockIdx.y * 128;

    uint32_t baseA[4], rxA[4];
    const uint32_t kqA = (uint32_t)(((lane >> 4) & 1) * 16);
    #pragma unroll
    for (int mi = 0; mi < 4; mi++) {
        int r = warpM * 64 + mi * 16 + (lane & 15);
        baseA[mi] = (uint32_t)(r * 128);
        rxA[mi]   = (uint32_t)((r & 7) * 16);
    }
    uint32_t baseB[2], rxB[2];
    const uint32_t kqB = (uint32_t)(((lane >> 3) & 1) * 16);
    #pragma unroll
    for (int np = 0; np < 2; np++) {
        int r = warpN * 32 + np * 16 + ((lane >> 4) & 1) * 8 + (lane & 7);
        baseB[np] = (uint32_t)(r * 128);
        rxB[np]   = (uint32_t)((r & 7) * 16);
    }

    float acc[4][4][4];
    #pragma unroll
    for (int mi = 0; mi < 4; mi++)
        #pragma unroll
        for (int ni = 0; ni < 4; ni++)
            #pragma unroll
            for (int c = 0; c < 4; c++) acc[mi][ni][c] = 0.0f;

    const __half* gA = g_Af16 + (size_t)rowBase * CNNC;
    const __half* gB = g_Bf16 + (size_t)colBase * CNNC;

    auto load_stage = [&](int slot, int kt) {
        const uint32_t aDst = sb + slot * STG_B;
        const uint32_t bDst = aDst + 128 * 128;
        const int kOff = kt * KCH;
        #pragma unroll
        for (int j = 0; j < 4; j++) {
            int c   = t + 256 * j;
            int row = c >> 3;
            int ch  = c & 7;
            uint32_t x = (uint32_t)(ch * 16) ^ (uint32_t)((row & 7) * 16);
            uint32_t d = (uint32_t)(row * 128) + x;
            cp_async16(aDst + d, gA + (size_t)row * CNNC + kOff + ch * 8);
            cp_async16(bDst + d, gB + (size_t)row * CNNC + kOff + ch * 8);
        }
    };

    // B-fragment loader for one ks into a [4][2] register set
    auto load_bf = [&](uint32_t bBase, int ks, uint32_t bf[4][2]) {
        const uint32_t kxB = (uint32_t)(ks * 32) + kqB;
        #pragma unroll
        for (int np = 0; np < 2; np++) {
            uint32_t r0, r1, r2, r3;
            ldsm_x4(r0, r1, r2, r3, bBase + baseB[np] + (kxB ^ rxB[np]));
            bf[np * 2 + 0][0] = r0; bf[np * 2 + 0][1] = r1;
            bf[np * 2 + 1][0] = r2; bf[np * 2 + 1][1] = r3;
        }
    };

    load_stage(0, 0); cp_commit();
    load_stage(1, 1); cp_commit();

    for (int kt = 0; kt < NSTG; kt++) {
        cp_wait1();
        __syncthreads();

        if (kt + 2 < NSTG) load_stage((kt + 2) % NRING, kt + 2);
        cp_commit();

        const uint32_t aBase = sb + (kt % NRING) * STG_B;
        const uint32_t bBase = aBase + 128 * 128;

        uint32_t bf[2][4][2];
        load_bf(bBase, 0, bf[0]);

        #pragma unroll
        for (int ks = 0; ks < 4; ks++) {
            const uint32_t kxA = (uint32_t)(ks * 32) + kqA;
            uint32_t af[4][4];
            #pragma unroll
            for (int mi = 0; mi < 4; mi++)
                ldsm_x4(af[mi][0], af[mi][1], af[mi][2], af[mi][3],
                        aBase + baseA[mi] + (kxA ^ rxA[mi]));
            if (ks < 3) load_bf(bBase, ks + 1, bf[(ks + 1) & 1]);
            #pragma unroll
            for (int mi = 0; mi < 4; mi++)
                #pragma unroll
                for (int ni = 0; ni < 4; ni++)
                    mma_f16(acc[mi][ni], af[mi], bf[ks & 1][ni]);
        }
    }

    // Epilogue: z[r] += sum_p tanh(V[r,p] + H'[b,p]) * w_attn[p]
    const int tig = lane & 3;
    const float* wcol = w_attn + colBase + warpN * 32;
    #pragma unroll
    for (int mi = 0; mi < 4; mi++) {
        #pragma unroll
        for (int h = 0; h < 2; h++) {
            int r = rowBase + warpM * 64 + mi * 16 + h * 8 + (lane >> 2);
            int bidx = r / GRID_G;
            const float* Hrow = g_H + (size_t)bidx * PROJ + colBase + warpN * 32;
            float s = 0.0f;
            #pragma unroll
            for (int ni = 0; ni < 4; ni++) {
                int p = ni * 8 + tig * 2;
                float v0 = acc[mi][ni][h * 2 + 0] + __ldg(Hrow + p);
                float v1 = acc[mi][ni][h * 2 + 1] + __ldg(Hrow + p + 1);
                s += tanh_ap(v0) * __ldg(wcol + p) + tanh_ap(v1) * __ldg(wcol + p + 1);
            }
            s += __shfl_xor_sync(0xffffffffu, s, 1);
            s += __shfl_xor_sync(0xffffffffu, s, 2);
            if (tig == 0) atomicAdd(&g_z[r], s);
        }
    }
}

// ===========================================================================
// Kernel 3: scramble + row softmax
// ===========================================================================
__global__ __launch_bounds__(64) void softmax_kernel(float* __restrict__ out)
{
    __shared__ float red[64];
    const int i = blockIdx.x;
    const int t = threadIdx.x;

    float v = -INFINITY;
    if (t < GRID_G) {
        int k = i * GRID_G + t;
        v = g_z[(k % BSZ) * GRID_G + (k / BSZ)];
    }
    red[t] = v;
    __syncthreads();
    #pragma unroll
    for (int s = 32; s > 0; s >>= 1) {
        if (t < s) red[t] = fmaxf(red[t], red[t + s]);
        __syncthreads();
    }
    float mx = red[0];
    __syncthreads();

    float e = (t < GRID_G) ? expf(v - mx) : 0.0f;
    red[t] = e;
    __syncthreads();
    #pragma unroll
    for (int s = 32; s > 0; s >>= 1) {
        if (t < s) red[t] += red[t + s];
        __syncthreads();
    }
    float sum = red[0];
    if (t < GRID_G) out[i * GRID_G + t] = e / sum;
}

// ===========================================================================
extern "C" void kernel_launch(void* const* d_in, const int* in_sizes, int n_in,
                              void* d_out, int out_size)
{
    const float* lstm = (const float*)d_in[0];
    const float* cnn  = (const float*)d_in[1];
    const float* Wl   = (const float*)d_in[2];
    const float* bl   = (const float*)d_in[3];
    const float* Wc   = (const float*)d_in[4];
    const float* bc   = (const float*)d_in[5];
    const float* wa   = (const float*)d_in[6];
    float* out = (float*)d_out;

    cudaFuncSetAttribute(attn_gemm_kernel,
                         cudaFuncAttributeMaxDynamicSharedMemorySize, ATT_SMEM);

    prep_kernel<<<H_BLOCKS + CONV_BLOCKS, 256>>>(lstm, Wl, bl, bc, cnn, Wc);
    attn_gemm_kernel<<<dim3(4, 98), 256, ATT_SMEM>>>(wa);
    softmax_kernel<<<256, 64>>>(out);
}